// round 5
// baseline (speedup 1.0000x reference)
#include <cuda_runtime.h>

#define DD 11
#define NTOK 49
#define SEQ 900
#define FFD 64
#define NT 256

__global__ __launch_bounds__(NT) void pve_kernel(
    const float* __restrict__ x,     // [10,16,16]
    const float* __restrict__ Wqkv,  // [33,11]
    const float* __restrict__ Wo,    // [11,11]
    const float* __restrict__ W1,    // [64,11]
    const float* __restrict__ W2,    // [11,64]
    const float* __restrict__ ln1,   // [11]
    const float* __restrict__ ln2,   // [11]
    float* __restrict__ out)         // [256,10,900]
{
    __shared__ float sWqkv[363];
    __shared__ float sWo[121];
    __shared__ float sW1[704];
    __shared__ float sW2t[704];      // transposed: [64][11]
    __shared__ float sln1[DD], sln2[DD];
    __shared__ float sX[50 * DD];    // token inputs (row 49 = zero token)
    __shared__ float sQ[50 * DD];
    __shared__ float sK[50 * DD];
    __shared__ float sV[50 * DD];
    __shared__ float sE[50 * NTOK];  // exp(scores)
    __shared__ float sZinv[50];
    __shared__ float sA[50 * DD];    // attn out; later reused for final LN2 out
    __shared__ float sR[50 * DD];    // Wo+residual; later reused for FF2 out
    __shared__ float sX1[50 * DD];   // LN1 out
    __shared__ float sH[50 * FFD];   // relu(FF1)
    __shared__ unsigned char tokmap[SEQ];

    const int tid = threadIdx.x;
    const int b  = blockIdx.x;
    const int ph = b >> 4;
    const int pw = b & 15;

    // ---- phase 1: stage weights, gather tokens, build token map ----
    for (int i = tid; i < 363; i += NT) sWqkv[i] = Wqkv[i];
    for (int i = tid; i < 121; i += NT) sWo[i]   = Wo[i];
    for (int i = tid; i < 704; i += NT) sW1[i]   = W1[i];
    for (int i = tid; i < 704; i += NT) {
        const int d = i / FFD, k = i - d * FFD;     // W2 is [11,64]
        sW2t[k * DD + d] = W2[i];
    }
    if (tid < DD) { sln1[tid] = ln1[tid]; sln2[tid] = ln2[tid]; }
    for (int idx = tid; idx < 50 * DD; idx += NT) { // idx = c*50 + t
        const int c = idx / 50, t = idx - c * 50;
        float v = 0.f;
        if (t < NTOK) {
            const int i = t / 7, j = t - i * 7;
            const int hh = ph + i - 3, ww = pw + j - 3;
            const bool inb = ((unsigned)hh < 16u) && ((unsigned)ww < 16u);
            if (c < 10) v = inb ? x[c * 256 + hh * 16 + ww] : 0.f;
            else        v = inb ? 0.f : 1.f;        // mask channel
        }
        sX[t * DD + c] = v;
    }
    for (int s = tid; s < SEQ; s += NT) {
        const int i = s / 30, j = s - i * 30;
        tokmap[s] = (i < 7 && j < 7) ? (unsigned char)(i * 7 + j) : (unsigned char)NTOK;
    }
    __syncthreads();

    // ---- phase 2: QKV = [50x11] @ [11x33] -> 1650 dot-11s ----
    for (int idx = tid; idx < 50 * 33; idx += NT) {
        const int row = idx / 33, col = idx - row * 33;
        float a = 0.f;
        #pragma unroll
        for (int e = 0; e < DD; e++) a += sX[row * DD + e] * sWqkv[col * DD + e];
        const int p = col / DD, d = col - p * DD;
        if (p == 0)      sQ[row * DD + d] = a;
        else if (p == 1) sK[row * DD + d] = a;
        else             sV[row * DD + d] = a;
    }
    __syncthreads();

    // ---- phase 3: scores + exp: 50x49 dot-11s ----
    {
        const float scale = rsqrtf(11.f);
        for (int idx = tid; idx < 50 * NTOK; idx += NT) {
            const int r = idx / NTOK, u = idx - r * NTOK;
            float s = 0.f;
            #pragma unroll
            for (int d = 0; d < DD; d++) s += sQ[r * DD + d] * sK[u * DD + d];
            sE[idx] = __expf(s * scale);
        }
    }
    __syncthreads();

    // ---- phase 4: A = E @ V (550 dot-49s) + Z (50 rowsums, items 550..599) ----
    for (int idx = tid; idx < 550 + 50; idx += NT) {
        if (idx < 550) {
            const int r = idx / DD, d = idx - r * DD;
            float a = 0.f;
            #pragma unroll
            for (int u = 0; u < NTOK; u++) a += sE[r * NTOK + u] * sV[u * DD + d];
            sA[idx] = a;
        } else {
            const int r = idx - 550;
            float z = 851.f;                 // 851 zero keys: exp(0)=1 each
            #pragma unroll
            for (int u = 0; u < NTOK; u++) z += sE[r * NTOK + u];
            sZinv[r] = 1.f / z;
        }
    }
    __syncthreads();

    // ---- phase 5: Wo proj + residual ----
    for (int idx = tid; idx < 550; idx += NT) {
        const int r = idx / DD, d = idx - r * DD;
        float a = 0.f;
        #pragma unroll
        for (int e = 0; e < DD; e++) a += sWo[d * DD + e] * sA[r * DD + e];
        sR[idx] = sX[idx] + a * sZinv[r];
    }
    __syncthreads();

    // ---- phase 5b: LayerNorm1 (50 threads) ----
    if (tid < 50) {
        float m = 0.f;
        #pragma unroll
        for (int d = 0; d < DD; d++) m += sR[tid * DD + d];
        m *= (1.f / 11.f);
        float v = 0.f;
        #pragma unroll
        for (int d = 0; d < DD; d++) { const float t = sR[tid * DD + d] - m; v += t * t; }
        const float rstd = rsqrtf(v * (1.f / 11.f) + 1e-5f);
        #pragma unroll
        for (int d = 0; d < DD; d++)
            sX1[tid * DD + d] = (sR[tid * DD + d] - m) * rstd * sln1[d];
    }
    __syncthreads();

    // ---- phase 6: FF1 + relu: 50x64 dot-11s ----
    for (int idx = tid; idx < 50 * FFD; idx += NT) {
        const int r = idx >> 6, f = idx & 63;
        float h = 0.f;
        #pragma unroll
        for (int d = 0; d < DD; d++) h += sW1[f * DD + d] * sX1[r * DD + d];
        sH[idx] = fmaxf(h, 0.f);
    }
    __syncthreads();

    // ---- phase 7: FF2 + residual: 550 dot-64s (into sR, reuse) ----
    for (int idx = tid; idx < 550; idx += NT) {
        const int r = idx / DD, d = idx - r * DD;
        float a = 0.f;
        #pragma unroll
        for (int k = 0; k < FFD; k++) a += sH[r * FFD + k] * sW2t[k * DD + d];
        sR[idx] = sX1[idx] + a;
    }
    __syncthreads();

    // ---- phase 7b: LayerNorm2 (50 threads) -> sA (reuse) ----
    if (tid < 50) {
        float m = 0.f;
        #pragma unroll
        for (int d = 0; d < DD; d++) m += sR[tid * DD + d];
        m *= (1.f / 11.f);
        float v = 0.f;
        #pragma unroll
        for (int d = 0; d < DD; d++) { const float t = sR[tid * DD + d] - m; v += t * t; }
        const float rstd = rsqrtf(v * (1.f / 11.f) + 1e-5f);
        #pragma unroll
        for (int d = 0; d < DD; d++)
            sA[tid * DD + d] = (sR[tid * DD + d] - m) * rstd * sln2[d];
    }
    __syncthreads();

    // ---- phase 8: coalesced scatter to out[b, c, s] ----
    float* ob = out + b * (10 * SEQ);
    #pragma unroll
    for (int c = 0; c < 10; c++)
        for (int s = tid; s < SEQ; s += NT)
            ob[c * SEQ + s] = sA[(int)tokmap[s] * DD + c];
}

extern "C" void kernel_launch(void* const* d_in, const int* in_sizes, int n_in,
                              void* d_out, int out_size) {
    const float* x    = (const float*)d_in[0];
    const float* Wqkv = (const float*)d_in[1];
    const float* Wo   = (const float*)d_in[2];
    const float* W1   = (const float*)d_in[3];
    const float* W2   = (const float*)d_in[4];
    const float* ln1  = (const float*)d_in[5];
    const float* ln2  = (const float*)d_in[6];
    float* out = (float*)d_out;
    pve_kernel<<<256, NT>>>(x, Wqkv, Wo, W1, W2, ln1, ln2, out);
}

// round 6
// speedup vs baseline: 1.0814x; 1.0814x over previous
#include <cuda_runtime.h>

#define DD 11
#define DP 12      // padded embed dim (float4-able)
#define NTOK 49
#define NTOKP 52   // padded, 16B-aligned rows
#define SEQ 900
#define FFD 64
#define FFP 68     // padded row stride (bank de-phasing)
#define NT 256

__device__ __forceinline__ float dot12(const float* __restrict__ a, const float* __restrict__ b) {
    const float4* A = (const float4*)a;
    const float4* B = (const float4*)b;
    float s = 0.f;
    #pragma unroll
    for (int i = 0; i < 3; i++) {
        float4 x = A[i], y = B[i];
        s += x.x * y.x + x.y * y.y + x.z * y.z + x.w * y.w;
    }
    return s;
}

__device__ __forceinline__ float dot52(const float* __restrict__ a, const float* __restrict__ b) {
    const float4* A = (const float4*)a;
    const float4* B = (const float4*)b;
    float s = 0.f;
    #pragma unroll
    for (int i = 0; i < 13; i++) {
        float4 x = A[i], y = B[i];
        s += x.x * y.x + x.y * y.y + x.z * y.z + x.w * y.w;
    }
    return s;
}

__device__ __forceinline__ float dot64(const float* __restrict__ a, const float* __restrict__ b) {
    const float4* A = (const float4*)a;
    const float4* B = (const float4*)b;
    float s = 0.f;
    #pragma unroll
    for (int i = 0; i < 16; i++) {
        float4 x = A[i], y = B[i];
        s += x.x * y.x + x.y * y.y + x.z * y.z + x.w * y.w;
    }
    return s;
}

__global__ __launch_bounds__(NT) void pve_kernel(
    const float* __restrict__ x,     // [10,16,16]
    const float* __restrict__ Wqkv,  // [33,11]
    const float* __restrict__ Wo,    // [11,11]
    const float* __restrict__ W1,    // [64,11]
    const float* __restrict__ W2,    // [11,64]
    const float* __restrict__ ln1,   // [11]
    const float* __restrict__ ln2,   // [11]
    float* __restrict__ out)         // [256,10,900]
{
    __shared__ __align__(16) float sWqkv[33 * DP];   // padded rows
    __shared__ __align__(16) float sWo[11 * DP];
    __shared__ __align__(16) float sW1[FFD * DP];
    __shared__ __align__(16) float sW2[11 * FFP];    // original [11][64] rows, stride 68
    __shared__ float sln1[DD], sln2[DD];
    __shared__ __align__(16) float sX[50 * DP];      // row 49 = zero token
    __shared__ __align__(16) float sQ[50 * DP];
    __shared__ __align__(16) float sK[50 * DP];
    __shared__ __align__(16) float sVt[11 * NTOKP];  // V transposed: [d][u]
    __shared__ __align__(16) float sE[50 * NTOKP];   // exp(scores), padded rows
    __shared__ float sZinv[50];
    __shared__ __align__(16) float sA[50 * DP];      // attn out; reused for LN2 out
    __shared__ __align__(16) float sR[50 * DP];
    __shared__ __align__(16) float sX1[50 * DP];     // LN1 out
    __shared__ __align__(16) float sH[50 * FFP];     // relu(FF1), stride 68

    const int tid = threadIdx.x;
    const int b  = blockIdx.x;
    const int ph = b >> 4;
    const int pw = b & 15;

    // ================= phase 1: stage weights (padded), tokens, zero pads =========
    for (int i = tid; i < 33 * DP; i += NT) {
        const int r = i / DP, e = i - r * DP;
        sWqkv[i] = (e < DD) ? Wqkv[r * DD + e] : 0.f;
    }
    for (int i = tid; i < 11 * DP; i += NT) {
        const int r = i / DP, e = i - r * DP;
        sWo[i] = (e < DD) ? Wo[r * DD + e] : 0.f;
    }
    for (int i = tid; i < FFD * DP; i += NT) {
        const int r = i / DP, e = i - r * DP;
        sW1[i] = (e < DD) ? W1[r * DD + e] : 0.f;
    }
    for (int i = tid; i < 11 * FFP; i += NT) {
        const int r = i / FFP, k = i - r * FFP;
        sW2[i] = (k < FFD) ? W2[r * FFD + k] : 0.f;
    }
    if (tid < DD) { sln1[tid] = ln1[tid]; sln2[tid] = ln2[tid]; }
    // token inputs
    for (int idx = tid; idx < 50 * DP; idx += NT) {
        const int t = idx / DP, c = idx - t * DP;
        float v = 0.f;
        if (t < NTOK && c < DD) {
            const int i = t / 7, j = t - i * 7;
            const int hh = ph + i - 3, ww = pw + j - 3;
            const bool inb = ((unsigned)hh < 16u) && ((unsigned)ww < 16u);
            if (c < 10) v = inb ? x[c * 256 + hh * 16 + ww] : 0.f;
            else        v = inb ? 0.f : 1.f;     // mask channel
        }
        sX[idx] = v;
    }
    // zero pad slots that vectorized dots will read
    for (int t = tid; t < 50; t += NT) {
        sQ[t * DP + DD] = 0.f; sK[t * DP + DD] = 0.f;
        sX1[t * DP + DD] = 0.f; sA[t * DP + DD] = 0.f;
    }
    for (int i = tid; i < 11 * 3; i += NT) {       // sVt row tails u=49..51
        const int d = i / 3, u = NTOK + (i - d * 3);
        sVt[d * NTOKP + u] = 0.f;
    }
    __syncthreads();

    // ================= phase 2: QKV  (50x33 dot-12s) =============================
    for (int idx = tid; idx < 50 * 33; idx += NT) {
        const int row = idx / 33, col = idx - row * 33;
        const float a = dot12(&sX[row * DP], &sWqkv[col * DP]);
        const int p = col / DD, d = col - p * DD;
        if (p == 0)      sQ[row * DP + d] = a;
        else if (p == 1) sK[row * DP + d] = a;
        else if (row < NTOK) sVt[d * NTOKP + row] = a;
    }
    __syncthreads();

    // ================= phase 3: E = exp(Q K^T * scale)  (50x52 incl pads) ========
    {
        const float scale = rsqrtf(11.f);
        for (int idx = tid; idx < 50 * NTOKP; idx += NT) {
            const int r = idx / NTOKP, u = idx - r * NTOKP;
            float e = 0.f;
            if (u < NTOK)
                e = __expf(dot12(&sQ[r * DP], &sK[u * DP]) * scale);
            sE[idx] = e;
        }
    }
    __syncthreads();

    // ================= phase 4: A = E @ V^T (dot-52s) + Z ========================
    for (int idx = tid; idx < 550 + 50; idx += NT) {
        if (idx < 550) {
            const int r = idx / DD, d = idx - r * DD;
            sA[r * DP + d] = dot52(&sE[r * NTOKP], &sVt[d * NTOKP]);
        } else {
            const int r = idx - 550;
            float z = 851.f;                        // 851 zero keys: exp(0)=1 each
            const float4* E = (const float4*)&sE[r * NTOKP];
            #pragma unroll
            for (int i = 0; i < 13; i++) {
                float4 v = E[i];
                z += v.x + v.y + v.z + v.w;
            }
            sZinv[r] = 1.f / z;
        }
    }
    __syncthreads();

    // ================= phase 5: Wo proj + residual ===============================
    for (int idx = tid; idx < 550; idx += NT) {
        const int r = idx / DD, d = idx - r * DD;
        sR[r * DP + d] = sX[r * DP + d] + dot12(&sWo[d * DP], &sA[r * DP]) * sZinv[r];
    }
    __syncthreads();

    // ---- LayerNorm1 (50 threads) ----
    if (tid < 50) {
        float m = 0.f;
        #pragma unroll
        for (int d = 0; d < DD; d++) m += sR[tid * DP + d];
        m *= (1.f / 11.f);
        float v = 0.f;
        #pragma unroll
        for (int d = 0; d < DD; d++) { const float t = sR[tid * DP + d] - m; v += t * t; }
        const float rstd = rsqrtf(v * (1.f / 11.f) + 1e-5f);
        #pragma unroll
        for (int d = 0; d < DD; d++)
            sX1[tid * DP + d] = (sR[tid * DP + d] - m) * rstd * sln1[d];
    }
    __syncthreads();

    // ================= phase 6: H = relu(X1 @ W1^T)  (50x64 dot-12s) =============
    for (int idx = tid; idx < 50 * FFD; idx += NT) {
        const int r = idx >> 6, f = idx & 63;
        sH[r * FFP + f] = fmaxf(dot12(&sW1[f * DP], &sX1[r * DP]), 0.f);
    }
    __syncthreads();

    // ================= phase 7: FF2 + residual (550 dot-64s) =====================
    for (int idx = tid; idx < 550; idx += NT) {
        const int r = idx / DD, d = idx - r * DD;
        sR[r * DP + d] = sX1[r * DP + d] + dot64(&sH[r * FFP], &sW2[d * FFP]);
    }
    __syncthreads();

    // ---- LayerNorm2 (50 threads) -> sA (reuse) ----
    if (tid < 50) {
        float m = 0.f;
        #pragma unroll
        for (int d = 0; d < DD; d++) m += sR[tid * DP + d];
        m *= (1.f / 11.f);
        float v = 0.f;
        #pragma unroll
        for (int d = 0; d < DD; d++) { const float t = sR[tid * DP + d] - m; v += t * t; }
        const float rstd = rsqrtf(v * (1.f / 11.f) + 1e-5f);
        #pragma unroll
        for (int d = 0; d < DD; d++)
            sA[tid * DP + d] = (sR[tid * DP + d] - m) * rstd * sln2[d];
    }
    __syncthreads();

    // ================= phase 8: output ==========================================
    // 851/900 positions per channel hold the zero-token value -> vectorized fill,
    // then overwrite the 49 window positions.
    float* ob = out + b * (10 * SEQ);
    for (int idx = tid; idx < 10 * (SEQ / 4); idx += NT) {   // 2250 float4
        const int c = idx / (SEQ / 4), q = idx - c * (SEQ / 4);
        const float z = sA[NTOK * DP + c];
        ((float4*)(ob + c * SEQ))[q] = make_float4(z, z, z, z);
    }
    __syncthreads();   // order fill before window overwrite (same CTA)
    for (int idx = tid; idx < 10 * NTOK; idx += NT) {
        const int c = idx / NTOK, w = idx - c * NTOK;
        const int i = w / 7, j = w - i * 7;
        ob[c * SEQ + i * 30 + j] = sA[w * DP + c];
    }
}

extern "C" void kernel_launch(void* const* d_in, const int* in_sizes, int n_in,
                              void* d_out, int out_size) {
    const float* x    = (const float*)d_in[0];
    const float* Wqkv = (const float*)d_in[1];
    const float* Wo   = (const float*)d_in[2];
    const float* W1   = (const float*)d_in[3];
    const float* W2   = (const float*)d_in[4];
    const float* ln1  = (const float*)d_in[5];
    const float* ln2  = (const float*)d_in[6];
    float* out = (float*)d_out;
    pve_kernel<<<256, NT>>>(x, Wqkv, Wo, W1, W2, ln1, ln2, out);
}

// round 9
// speedup vs baseline: 1.0947x; 1.0122x over previous
#include <cuda_runtime.h>

#define DD 11
#define DP 12      // padded embed dim
#define NTOK 49
#define NTOKP 52
#define SEQ 900
#define FFD 64
#define FFP 68
#define NT 512

// ---- device scratch (no allocs allowed) ----
// blob layout: Wo[11*12] @0, W1[64*12] @132, W2[11*68] @900, ln1 @1648 (12), ln2 @1660 (12), pad->1680
#define BLOB_WO   0
#define BLOB_W1   132
#define BLOB_W2   900
#define BLOB_LN1  1648
#define BLOB_LN2  1660
#define BLOB_SZ   1680
__device__ float g_blob[BLOB_SZ];
// per-token qkv, padded: [258][36]: q@0 (prescaled by 1/sqrt(11)), k@12, v@24; slot 11/23/35 = 0
// token 0..255 = pixel, 256 = border (mask=1), 257 = zero token
__device__ float g_qkv[258 * 36];

__device__ __forceinline__ float dot12(const float* __restrict__ a, const float* __restrict__ b) {
    const float4* A = (const float4*)a;
    const float4* B = (const float4*)b;
    float s = 0.f;
    #pragma unroll
    for (int i = 0; i < 3; i++) {
        float4 x = A[i], y = B[i];
        s += x.x * y.x + x.y * y.y + x.z * y.z + x.w * y.w;
    }
    return s;
}

__device__ __forceinline__ float dot52(const float* __restrict__ a, const float* __restrict__ b) {
    const float4* A = (const float4*)a;
    const float4* B = (const float4*)b;
    float s = 0.f;
    #pragma unroll
    for (int i = 0; i < 13; i++) {
        float4 x = A[i], y = B[i];
        s += x.x * y.x + x.y * y.y + x.z * y.z + x.w * y.w;
    }
    return s;
}

__device__ __forceinline__ float dot64(const float* __restrict__ a, const float* __restrict__ b) {
    const float4* A = (const float4*)a;
    const float4* B = (const float4*)b;
    float s = 0.f;
    #pragma unroll
    for (int i = 0; i < 16; i++) {
        float4 x = A[i], y = B[i];
        s += x.x * y.x + x.y * y.y + x.z * y.z + x.w * y.w;
    }
    return s;
}

// ===================== K0: precompute blob + per-token QKV =====================
__global__ __launch_bounds__(256) void pve_prep(
    const float* __restrict__ x,     // [10,16,16]
    const float* __restrict__ Wqkv,  // [33,11]
    const float* __restrict__ Wo,
    const float* __restrict__ W1,
    const float* __restrict__ W2,
    const float* __restrict__ ln1,
    const float* __restrict__ ln2)
{
    const int cta = blockIdx.x;
    const int tid = threadIdx.x;
    if (cta < 37) {
        const int item = cta * 256 + tid;
        if (item < 258 * 33) {
            const int t = item / 33, col = item - t * 33;
            float xv[DD];
            #pragma unroll
            for (int c = 0; c < DD; c++) xv[c] = 0.f;
            if (t < 256) {
                #pragma unroll
                for (int c = 0; c < 10; c++) xv[c] = x[c * 256 + t];
            } else if (t == 256) {
                xv[10] = 1.f;       // border token: only mask channel
            }                       // t==257: zero token
            const float* wr = Wqkv + col * DD;
            float a = 0.f;
            #pragma unroll
            for (int e = 0; e < DD; e++) a += wr[e] * xv[e];
            const int part = col / DD, d = col - part * DD;
            if (part == 0) a *= rsqrtf(11.f);   // pre-scale q
            g_qkv[t * 36 + part * DP + d] = a;
        } else if (item < 258 * 33 + 258 * 3) {
            const int p = item - 258 * 33;
            const int t = p / 3, part = p - t * 3;
            g_qkv[t * 36 + part * DP + DD] = 0.f;   // pad slots
        }
    } else {
        // blob CTA
        for (int i = tid; i < BLOB_SZ; i += 256) {
            float v = 0.f;
            if (i < BLOB_W1) {
                const int r = i / DP, e = i - r * DP;
                if (e < DD) v = Wo[r * DD + e];
            } else if (i < BLOB_W2) {
                const int j = i - BLOB_W1;
                const int r = j / DP, e = j - r * DP;
                if (e < DD) v = W1[r * DD + e];
            } else if (i < BLOB_LN1) {
                const int j = i - BLOB_W2;
                const int r = j / FFP, k = j - r * FFP;
                if (k < FFD) v = W2[r * FFD + k];
            } else if (i < BLOB_LN2) {
                const int e = i - BLOB_LN1;
                if (e < DD) v = ln1[e];
            } else {
                const int e = i - BLOB_LN2;
                if (e < DD && i < BLOB_LN2 + DP) v = ln2[e];
            }
            g_blob[i] = v;
        }
    }
}

// ===================== K2: main per-pixel transformer =====================
__global__ __launch_bounds__(NT) void pve_main(
    const float* __restrict__ x,     // [10,16,16]
    float* __restrict__ out)         // [256,10,900]
{
    __shared__ __align__(16) float sBlob[BLOB_SZ];
    __shared__ __align__(16) float sX[50 * DP];
    __shared__ __align__(16) float sQ[50 * DP];
    __shared__ __align__(16) float sK[50 * DP];
    __shared__ __align__(16) float sVt[DD * NTOKP];
    __shared__ __align__(16) float sPool[50 * FFP];   // sE (50*52) then sH (50*68)
    __shared__ float sZinv[50];
    __shared__ __align__(16) float sA[50 * DP];       // attn out; reused for LN2 out
    __shared__ __align__(16) float sR[50 * DP];
    __shared__ __align__(16) float sX1[50 * DP];
    __shared__ int tokid[50];

    float* sE = sPool;
    float* sH = sPool;

    const int tid = threadIdx.x;
    const int b  = blockIdx.x;
    const int ph = b >> 4;
    const int pw = b & 15;

    // ---- phase 1a: blob copy + token ids ----
    for (int i = tid; i < BLOB_SZ / 4; i += NT)
        ((float4*)sBlob)[i] = ((const float4*)g_blob)[i];
    if (tid < 50) {
        int tk = 257;                       // zero token
        if (tid < NTOK) {
            const int i = tid / 7, j = tid - i * 7;
            const int hh = ph + i - 3, ww = pw + j - 3;
            tk = (((unsigned)hh < 16u) && ((unsigned)ww < 16u)) ? (hh * 16 + ww) : 256;
        }
        tokid[tid] = tk;
    }
    __syncthreads();

    // ---- phase 1b: gather q,k (float4), x (scalar), v transposed ----
    for (int idx = tid; idx < 300; idx += NT) {       // 50 tokens x 6 float4
        const int t = idx / 6, w = idx - t * 6;
        const float4 val = ((const float4*)(g_qkv + tokid[t] * 36))[w];
        if (w < 3) ((float4*)(sQ + t * DP))[w] = val;
        else       ((float4*)(sK + t * DP))[w - 3] = val;
    }
    for (int idx = tid; idx < 50 * DP; idx += NT) {   // token inputs (residual)
        const int t = idx / DP, c = idx - t * DP;
        const int tk = tokid[t];
        float v = 0.f;
        if (c < DD && tk < 257) {
            if (tk < 256) { if (c < 10) v = x[c * 256 + tk]; }
            else          { if (c == 10) v = 1.f; }
        }
        sX[idx] = v;
    }
    for (int idx = tid; idx < 550; idx += NT) {       // V transposed [d][u]
        const int t = idx / DD, d = idx - t * DD;
        if (t < NTOK) sVt[d * NTOKP + t] = g_qkv[tokid[t] * 36 + 24 + d];
    }
    for (int i = tid; i < DD * 3; i += NT) {          // Vt pad tails
        const int d = i / 3;
        sVt[d * NTOKP + NTOK + (i - d * 3)] = 0.f;
    }
    __syncthreads();

    // ---- phase 2: E = exp(q.k) (q pre-scaled) ----
    for (int idx = tid; idx < 50 * NTOKP; idx += NT) {
        const int r = idx / NTOKP, u = idx - r * NTOKP;
        sE[idx] = (u < NTOK) ? __expf(dot12(&sQ[r * DP], &sK[u * DP])) : 0.f;
    }
    __syncthreads();

    // ---- phase 3: A = E @ V^T, Z ----
    for (int idx = tid; idx < 600; idx += NT) {
        if (idx < 550) {
            const int r = idx / DD, d = idx - r * DD;
            sA[r * DP + d] = dot52(&sE[r * NTOKP], &sVt[d * NTOKP]);
        } else {
            const int r = idx - 550;
            float z = 851.f;
            const float4* E = (const float4*)&sE[r * NTOKP];
            #pragma unroll
            for (int i = 0; i < 13; i++) {
                const float4 v = E[i];
                z += v.x + v.y + v.z + v.w;
            }
            sZinv[r] = 1.f / z;
        }
    }
    __syncthreads();

    // ---- phase 4: Wo proj + residual ----
    for (int idx = tid; idx < 550; idx += NT) {
        const int r = idx / DD, d = idx - r * DD;
        sR[r * DP + d] = sX[r * DP + d] +
                         dot12(&sBlob[BLOB_WO + d * DP], &sA[r * DP]) * sZinv[r];
    }
    __syncthreads();

    // ---- LayerNorm1 ----
    if (tid < 50) {
        float m = 0.f;
        #pragma unroll
        for (int d = 0; d < DD; d++) m += sR[tid * DP + d];
        m *= (1.f / 11.f);
        float v = 0.f;
        #pragma unroll
        for (int d = 0; d < DD; d++) { const float t = sR[tid * DP + d] - m; v += t * t; }
        const float rstd = rsqrtf(v * (1.f / 11.f) + 1e-5f);
        #pragma unroll
        for (int d = 0; d < DD; d++)
            sX1[tid * DP + d] = (sR[tid * DP + d] - m) * rstd * sBlob[BLOB_LN1 + d];
        sX1[tid * DP + DD] = 0.f;
    }
    __syncthreads();

    // ---- phase 6: H = relu(X1 @ W1^T) ----
    for (int idx = tid; idx < 50 * FFD; idx += NT) {
        const int r = idx >> 6, f = idx & 63;
        sH[r * FFP + f] = fmaxf(dot12(&sBlob[BLOB_W1 + f * DP], &sX1[r * DP]), 0.f);
    }
    for (int i = tid; i < 50 * 4; i += NT) {          // H pad tails (64..67)
        const int r = i >> 2;
        sH[r * FFP + FFD + (i & 3)] = 0.f;
    }
    __syncthreads();

    // ---- phase 7: FF2 + residual ----
    for (int idx = tid; idx < 550; idx += NT) {
        const int r = idx / DD, d = idx - r * DD;
        sR[r * DP + d] = sX1[r * DP + d] +
                         dot64(&sH[r * FFP], &sBlob[BLOB_W2 + d * FFP]);
    }
    __syncthreads();

    // ---- LayerNorm2 -> sA ----
    if (tid < 50) {
        float m = 0.f;
        #pragma unroll
        for (int d = 0; d < DD; d++) m += sR[tid * DP + d];
        m *= (1.f / 11.f);
        float v = 0.f;
        #pragma unroll
        for (int d = 0; d < DD; d++) { const float t = sR[tid * DP + d] - m; v += t * t; }
        const float rstd = rsqrtf(v * (1.f / 11.f) + 1e-5f);
        #pragma unroll
        for (int d = 0; d < DD; d++)
            sA[tid * DP + d] = (sR[tid * DP + d] - m) * rstd * sBlob[BLOB_LN2 + d];
    }
    __syncthreads();

    // ---- phase 8: output: broadcast fill then window overwrite ----
    float* ob = out + b * (10 * SEQ);
    for (int idx = tid; idx < 10 * (SEQ / 4); idx += NT) {
        const int c = idx / (SEQ / 4), q = idx - c * (SEQ / 4);
        const float z = sA[NTOK * DP + c];
        ((float4*)(ob + c * SEQ))[q] = make_float4(z, z, z, z);
    }
    __syncthreads();
    for (int idx = tid; idx < 10 * NTOK; idx += NT) {
        const int c = idx / NTOK, w = idx - c * NTOK;
        const int i = w / 7, j = w - i * 7;
        ob[c * SEQ + i * 30 + j] = sA[w * DP + c];
    }
}

extern "C" void kernel_launch(void* const* d_in, const int* in_sizes, int n_in,
                              void* d_out, int out_size) {
    const float* x    = (const float*)d_in[0];
    const float* Wqkv = (const float*)d_in[1];
    const float* Wo   = (const float*)d_in[2];
    const float* W1   = (const float*)d_in[3];
    const float* W2   = (const float*)d_in[4];
    const float* ln1  = (const float*)d_in[5];
    const float* ln2  = (const float*)d_in[6];
    float* out = (float*)d_out;
    pve_prep<<<38, 256>>>(x, Wqkv, Wo, W1, W2, ln1, ln2);
    pve_main<<<256, NT>>>(x, out);
}